// round 1
// baseline (speedup 1.0000x reference)
#include <cuda_runtime.h>
#include <cstdint>

// Problem constants (fixed shapes per reference setup_inputs)
#define D_FEAT   300
#define D_VEC4   75            // 300 / 4
#define G_MAX    8192
#define N_ROWS_MAXGUARD 0      // rows come from in_sizes

// Fused affine coefficients per (segment, feature):
//   out = a * x + b   where a = w * inv_std, b = bias - a * mean
// float4 arrays => 16B-aligned for vector loads in the apply pass.
__device__ float4 g_a4[G_MAX * D_VEC4];
__device__ float4 g_b4[G_MAX * D_VEC4];

// ---------------------------------------------------------------------------
// Kernel 1: per-segment stats. One block per segment (segment_ids is sorted,
// so each segment is a contiguous row range found via binary search).
// blockDim = 320 (300 active threads, one feature column each).
// ---------------------------------------------------------------------------
__global__ __launch_bounds__(320)
void seg_stats_kernel(const float* __restrict__ x,
                      const float* __restrict__ weight,
                      const float* __restrict__ bias,
                      const int*   __restrict__ seg,
                      int N)
{
    const int g = blockIdx.x;

    __shared__ int s_start, s_end;
    if (threadIdx.x == 0) {
        // lower_bound(seg, g)
        int lo = 0, hi = N;
        while (lo < hi) { int m = (lo + hi) >> 1; if (seg[m] < g) lo = m + 1; else hi = m; }
        s_start = lo;
        // lower_bound(seg, g+1), starting from lo
        int lo2 = lo; hi = N;
        while (lo2 < hi) { int m = (lo2 + hi) >> 1; if (seg[m] < g + 1) lo2 = m + 1; else hi = m; }
        s_end = lo2;
    }
    __syncthreads();

    const int start = s_start;
    const int end   = s_end;
    const int tid   = threadIdx.x;
    if (tid >= D_FEAT) return;

    const int cnt = end - start;

    float sum = 0.f, sq = 0.f;
    const float* p = x + (size_t)start * D_FEAT + tid;

    int r = 0;
    // unroll x4 for memory-level parallelism
    for (; r + 4 <= cnt; r += 4) {
        float v0 = p[0];
        float v1 = p[D_FEAT];
        float v2 = p[2 * D_FEAT];
        float v3 = p[3 * D_FEAT];
        p += 4 * D_FEAT;
        sum += (v0 + v1) + (v2 + v3);
        sq  = fmaf(v0, v0, sq);
        sq  = fmaf(v1, v1, sq);
        sq  = fmaf(v2, v2, sq);
        sq  = fmaf(v3, v3, sq);
    }
    for (; r < cnt; ++r) {
        float v = *p; p += D_FEAT;
        sum += v;
        sq  = fmaf(v, v, sq);
    }

    const float c    = (float)max(cnt, 1);
    const float rc   = 1.0f / c;
    const float mean = sum * rc;
    float var = fmaf(sq, rc, -mean * mean);   // E[x^2] - mean^2
    var = fmaxf(var, 0.0f);
    const float inv  = rsqrtf(var + 1e-6f);

    const float w = weight[tid];
    const float b = bias[tid];
    const float a = w * inv;

    float* a_f = reinterpret_cast<float*>(g_a4);
    float* b_f = reinterpret_cast<float*>(g_b4);
    const size_t idx = (size_t)g * D_FEAT + tid;
    a_f[idx] = a;
    b_f[idx] = b - a * mean;
}

// ---------------------------------------------------------------------------
// Kernel 2: apply. Flat float4 grid over all N*75 vectors.
// Coefficient arrays (~20 MB) are L2-resident; each (g,col) element is reused
// ~61x across the rows of its segment.
// ---------------------------------------------------------------------------
__global__ __launch_bounds__(256)
void seg_apply_kernel(const float4* __restrict__ x4,
                      const int*    __restrict__ seg,
                      float4*       __restrict__ out4,
                      int totalV)
{
    const int v = blockIdx.x * blockDim.x + threadIdx.x;
    if (v >= totalV) return;

    const unsigned uv  = (unsigned)v;
    const unsigned row = uv / (unsigned)D_VEC4;          // constant division -> mul
    const unsigned c4  = uv - row * (unsigned)D_VEC4;

    const int g = __ldg(seg + row);
    const size_t si = (size_t)g * D_VEC4 + c4;

    const float4 xv = x4[v];
    const float4 av = __ldg(&g_a4[si]);
    const float4 bv = __ldg(&g_b4[si]);

    float4 o;
    o.x = fmaf(av.x, xv.x, bv.x);
    o.y = fmaf(av.y, xv.y, bv.y);
    o.z = fmaf(av.z, xv.z, bv.z);
    o.w = fmaf(av.w, xv.w, bv.w);
    out4[v] = o;
}

// ---------------------------------------------------------------------------
// Launch. Inputs (metadata order): tensor [N,300] f32, weight [300] f32,
// bias [300] f32, segment_ids [N] i32, num_graphs scalar i32.
// num_graphs is fixed at 8192; blocks for nonexistent segments find an empty
// row range and write benign values that are never read.
// ---------------------------------------------------------------------------
extern "C" void kernel_launch(void* const* d_in, const int* in_sizes, int n_in,
                              void* d_out, int out_size)
{
    const float* tensor = (const float*)d_in[0];
    const float* weight = (const float*)d_in[1];
    const float* bias   = (const float*)d_in[2];
    const int*   seg    = (const int*)d_in[3];

    const int N = in_sizes[3];                 // number of rows (segment_ids count)

    // Pass 1: per-segment stats -> fused affine coefficients
    seg_stats_kernel<<<G_MAX, 320>>>(tensor, weight, bias, seg, N);

    // Pass 2: apply
    const long long totalV = (long long)N * D_VEC4;
    const int threads = 256;
    const int blocks  = (int)((totalV + threads - 1) / threads);
    seg_apply_kernel<<<blocks, threads>>>((const float4*)tensor, seg,
                                          (float4*)d_out, (int)totalV);
}

// round 2
// speedup vs baseline: 1.6200x; 1.6200x over previous
#include <cuda_runtime.h>
#include <cstdint>

// Fixed problem shape (per reference setup_inputs): N=500000 rows, D=300, G=8192.
#define D_FEAT 300
#define D_VEC4 75          // 300/4
#define G_MAX  8192
#define EPS    1e-6f

// ---------------------------------------------------------------------------
// Fused kernel: one block per segment (segment_ids sorted -> contiguous range).
// blockDim = 320 (300 active = 75 float4-columns x 4 row-groups).
// Phase 1: per-feature sum/sumsq (float4 loads, 4-way row parallelism).
// Phase 2: re-stream the segment (L2-hot) applying out = a*x + b.
// ---------------------------------------------------------------------------
__global__ __launch_bounds__(320)
void fused_instnorm_kernel(const float4* __restrict__ x4,
                           const float*  __restrict__ weight,
                           const float*  __restrict__ bias,
                           const int*    __restrict__ seg,
                           float4*       __restrict__ out4,
                           int N)
{
    const int g = blockIdx.x;

    __shared__ int    s_bounds[2];
    __shared__ float4 s_sum[4][D_VEC4];
    __shared__ float4 s_sq [4][D_VEC4];
    __shared__ float4 s_a[D_VEC4];
    __shared__ float4 s_b[D_VEC4];

    // Two parallel binary searches: lower_bound(g) and lower_bound(g+1)
    if (threadIdx.x < 2) {
        const int target = g + (int)threadIdx.x;
        int lo = 0, hi = N;
        while (lo < hi) {
            int m = (lo + hi) >> 1;
            if (seg[m] < target) lo = m + 1; else hi = m;
        }
        s_bounds[threadIdx.x] = lo;
    }
    __syncthreads();

    const int start = s_bounds[0];
    const int cnt   = s_bounds[1] - start;
    const int tid   = threadIdx.x;

    const int c4 = tid % D_VEC4;   // float4 column (0..74)
    const int rg = tid / D_VEC4;   // row group (0..3) for tid < 300

    // ---------------- Phase 1: reduce sum / sumsq ----------------
    if (tid < 300) {
        float4 sum = make_float4(0.f, 0.f, 0.f, 0.f);
        float4 sq  = make_float4(0.f, 0.f, 0.f, 0.f);
        const float4* p = x4 + (size_t)start * D_VEC4 + c4;

        #pragma unroll 4
        for (int r = rg; r < cnt; r += 4) {
            const float4 v = p[(size_t)r * D_VEC4];
            sum.x += v.x; sum.y += v.y; sum.z += v.z; sum.w += v.w;
            sq.x = fmaf(v.x, v.x, sq.x);
            sq.y = fmaf(v.y, v.y, sq.y);
            sq.z = fmaf(v.z, v.z, sq.z);
            sq.w = fmaf(v.w, v.w, sq.w);
        }
        s_sum[rg][c4] = sum;
        s_sq [rg][c4] = sq;
    }
    __syncthreads();

    // ---------------- Coefficients: a = w*rsqrt(var+eps), b = bias - a*mean ----
    if (tid < D_VEC4) {
        float4 s0 = s_sum[0][tid], s1 = s_sum[1][tid],
               s2 = s_sum[2][tid], s3 = s_sum[3][tid];
        float4 q0 = s_sq[0][tid], q1 = s_sq[1][tid],
               q2 = s_sq[2][tid], q3 = s_sq[3][tid];

        float4 s, q;
        s.x = (s0.x + s1.x) + (s2.x + s3.x);
        s.y = (s0.y + s1.y) + (s2.y + s3.y);
        s.z = (s0.z + s1.z) + (s2.z + s3.z);
        s.w = (s0.w + s1.w) + (s2.w + s3.w);
        q.x = (q0.x + q1.x) + (q2.x + q3.x);
        q.y = (q0.y + q1.y) + (q2.y + q3.y);
        q.z = (q0.z + q1.z) + (q2.z + q3.z);
        q.w = (q0.w + q1.w) + (q2.w + q3.w);

        const float rc = 1.0f / (float)max(cnt, 1);
        const float4 w4 = __ldg(&((const float4*)weight)[tid]);
        const float4 b4 = __ldg(&((const float4*)bias)[tid]);

        float4 a, bb;
        {
            float mean = s.x * rc;
            float var  = fmaxf(fmaf(q.x, rc, -mean * mean), 0.f);
            a.x  = w4.x * rsqrtf(var + EPS);
            bb.x = b4.x - a.x * mean;
        }
        {
            float mean = s.y * rc;
            float var  = fmaxf(fmaf(q.y, rc, -mean * mean), 0.f);
            a.y  = w4.y * rsqrtf(var + EPS);
            bb.y = b4.y - a.y * mean;
        }
        {
            float mean = s.z * rc;
            float var  = fmaxf(fmaf(q.z, rc, -mean * mean), 0.f);
            a.z  = w4.z * rsqrtf(var + EPS);
            bb.z = b4.z - a.z * mean;
        }
        {
            float mean = s.w * rc;
            float var  = fmaxf(fmaf(q.w, rc, -mean * mean), 0.f);
            a.w  = w4.w * rsqrtf(var + EPS);
            bb.w = b4.w - a.w * mean;
        }
        s_a[tid] = a;
        s_b[tid] = bb;
    }
    __syncthreads();

    // ---------------- Phase 2: apply (segment rows L2-hot) ----------------
    if (tid < 300) {
        const float4 a  = s_a[c4];
        const float4 bb = s_b[c4];
        const float4* p = x4   + (size_t)start * D_VEC4 + c4;
        float4*       o = out4 + (size_t)start * D_VEC4 + c4;

        #pragma unroll 4
        for (int r = rg; r < cnt; r += 4) {
            const float4 v = p[(size_t)r * D_VEC4];
            float4 res;
            res.x = fmaf(a.x, v.x, bb.x);
            res.y = fmaf(a.y, v.y, bb.y);
            res.z = fmaf(a.z, v.z, bb.z);
            res.w = fmaf(a.w, v.w, bb.w);
            o[(size_t)r * D_VEC4] = res;
        }
    }
}

// ---------------------------------------------------------------------------
// Inputs (metadata order): tensor [N,300] f32, weight [300] f32,
// bias [300] f32, segment_ids [N] i32, num_graphs scalar i32 (= 8192).
// ---------------------------------------------------------------------------
extern "C" void kernel_launch(void* const* d_in, const int* in_sizes, int n_in,
                              void* d_out, int out_size)
{
    const float* tensor = (const float*)d_in[0];
    const float* weight = (const float*)d_in[1];
    const float* bias   = (const float*)d_in[2];
    const int*   seg    = (const int*)d_in[3];
    const int N = in_sizes[3];

    fused_instnorm_kernel<<<G_MAX, 320>>>((const float4*)tensor, weight, bias,
                                          seg, (float4*)d_out, N);
}

// round 3
// speedup vs baseline: 1.7608x; 1.0869x over previous
#include <cuda_runtime.h>
#include <cstdint>

// Fixed problem shape (per reference setup_inputs): N=500000 rows, D=300, G=8192.
#define D_FEAT 300
#define D_VEC4 75          // 300/4
#define G_MAX  8192
#define EPS    1e-6f

// Precomputed segment boundaries: offs[g] = first row of segment g, offs[G]=N.
__device__ int g_offs[G_MAX + 1];

// ---------------------------------------------------------------------------
// Kernel 0: segment boundary precompute (segment_ids sorted).
// offs[g] = lower_bound(seg, g). Each thread handles the (seg[i-1], seg[i]]
// gap; total fill work across threads == G.
// ---------------------------------------------------------------------------
__global__ __launch_bounds__(256)
void boundaries_kernel(const int* __restrict__ seg, int N)
{
    const int i = blockIdx.x * blockDim.x + threadIdx.x;
    if (i >= N) return;
    const int cur  = seg[i];
    const int prev = (i == 0) ? -1 : seg[i - 1];
    for (int g = prev + 1; g <= cur; ++g) g_offs[g] = i;
    if (i == N - 1) {
        for (int g = cur + 1; g <= G_MAX; ++g) g_offs[g] = N;
    }
}

// ---------------------------------------------------------------------------
// Fused kernel: one block per segment (contiguous row range from g_offs).
// blockDim = 320 (300 active = 75 float4-columns x 4 row-groups).
// Phase 1: per-feature sum/sumsq (float4 loads, 4-way row parallelism).
// Phase 2: re-stream the segment (L2-hot) applying out = a*x + b.
// ---------------------------------------------------------------------------
__global__ __launch_bounds__(320)
void fused_instnorm_kernel(const float4* __restrict__ x4,
                           const float*  __restrict__ weight,
                           const float*  __restrict__ bias,
                           float4*       __restrict__ out4)
{
    const int g = blockIdx.x;

    __shared__ float4 s_sum[4][D_VEC4];
    __shared__ float4 s_sq [4][D_VEC4];
    __shared__ float4 s_a[D_VEC4];
    __shared__ float4 s_b[D_VEC4];

    const int start = g_offs[g];
    const int cnt   = g_offs[g + 1] - start;
    const int tid   = threadIdx.x;

    const int c4 = tid % D_VEC4;   // float4 column (0..74)
    const int rg = tid / D_VEC4;   // row group (0..3) for tid < 300

    // ---------------- Phase 1: reduce sum / sumsq ----------------
    if (tid < 300) {
        float4 sum = make_float4(0.f, 0.f, 0.f, 0.f);
        float4 sq  = make_float4(0.f, 0.f, 0.f, 0.f);
        const float4* p = x4 + (size_t)start * D_VEC4 + c4;

        #pragma unroll 8
        for (int r = rg; r < cnt; r += 4) {
            const float4 v = p[(size_t)r * D_VEC4];
            sum.x += v.x; sum.y += v.y; sum.z += v.z; sum.w += v.w;
            sq.x = fmaf(v.x, v.x, sq.x);
            sq.y = fmaf(v.y, v.y, sq.y);
            sq.z = fmaf(v.z, v.z, sq.z);
            sq.w = fmaf(v.w, v.w, sq.w);
        }
        s_sum[rg][c4] = sum;
        s_sq [rg][c4] = sq;
    }
    __syncthreads();

    // ------- Coefficients: a = w*rsqrt(var+eps), b = bias - a*mean -------
    if (tid < D_VEC4) {
        float4 s0 = s_sum[0][tid], s1 = s_sum[1][tid],
               s2 = s_sum[2][tid], s3 = s_sum[3][tid];
        float4 q0 = s_sq[0][tid], q1 = s_sq[1][tid],
               q2 = s_sq[2][tid], q3 = s_sq[3][tid];

        float4 s, q;
        s.x = (s0.x + s1.x) + (s2.x + s3.x);
        s.y = (s0.y + s1.y) + (s2.y + s3.y);
        s.z = (s0.z + s1.z) + (s2.z + s3.z);
        s.w = (s0.w + s1.w) + (s2.w + s3.w);
        q.x = (q0.x + q1.x) + (q2.x + q3.x);
        q.y = (q0.y + q1.y) + (q2.y + q3.y);
        q.z = (q0.z + q1.z) + (q2.z + q3.z);
        q.w = (q0.w + q1.w) + (q2.w + q3.w);

        const float rc = 1.0f / (float)max(cnt, 1);
        const float4 w4 = __ldg(&((const float4*)weight)[tid]);
        const float4 b4 = __ldg(&((const float4*)bias)[tid]);

        float4 a, bb;
        {
            float mean = s.x * rc;
            float var  = fmaxf(fmaf(q.x, rc, -mean * mean), 0.f);
            a.x  = w4.x * rsqrtf(var + EPS);
            bb.x = b4.x - a.x * mean;
        }
        {
            float mean = s.y * rc;
            float var  = fmaxf(fmaf(q.y, rc, -mean * mean), 0.f);
            a.y  = w4.y * rsqrtf(var + EPS);
            bb.y = b4.y - a.y * mean;
        }
        {
            float mean = s.z * rc;
            float var  = fmaxf(fmaf(q.z, rc, -mean * mean), 0.f);
            a.z  = w4.z * rsqrtf(var + EPS);
            bb.z = b4.z - a.z * mean;
        }
        {
            float mean = s.w * rc;
            float var  = fmaxf(fmaf(q.w, rc, -mean * mean), 0.f);
            a.w  = w4.w * rsqrtf(var + EPS);
            bb.w = b4.w - a.w * mean;
        }
        s_a[tid] = a;
        s_b[tid] = bb;
    }
    __syncthreads();

    // ---------------- Phase 2: apply (segment rows L2-hot) ----------------
    if (tid < 300) {
        const float4 a  = s_a[c4];
        const float4 bb = s_b[c4];
        const float4* p = x4   + (size_t)start * D_VEC4 + c4;
        float4*       o = out4 + (size_t)start * D_VEC4 + c4;

        #pragma unroll 8
        for (int r = rg; r < cnt; r += 4) {
            // last-use load: L2 hit from phase 1, mark evict-first
            const float4 v = __ldcs(&p[(size_t)r * D_VEC4]);
            float4 res;
            res.x = fmaf(a.x, v.x, bb.x);
            res.y = fmaf(a.y, v.y, bb.y);
            res.z = fmaf(a.z, v.z, bb.z);
            res.w = fmaf(a.w, v.w, bb.w);
            // streaming store: never re-read, keep out of L2
            __stcs(&o[(size_t)r * D_VEC4], res);
        }
    }
}

// ---------------------------------------------------------------------------
// Inputs (metadata order): tensor [N,300] f32, weight [300] f32,
// bias [300] f32, segment_ids [N] i32, num_graphs scalar i32 (= 8192).
// ---------------------------------------------------------------------------
extern "C" void kernel_launch(void* const* d_in, const int* in_sizes, int n_in,
                              void* d_out, int out_size)
{
    const float* tensor = (const float*)d_in[0];
    const float* weight = (const float*)d_in[1];
    const float* bias   = (const float*)d_in[2];
    const int*   seg    = (const int*)d_in[3];
    const int N = in_sizes[3];

    boundaries_kernel<<<(N + 255) / 256, 256>>>(seg, N);
    fused_instnorm_kernel<<<G_MAX, 320>>>((const float4*)tensor, weight, bias,
                                          (float4*)d_out);
}